// round 3
// baseline (speedup 1.0000x reference)
#include <cuda_runtime.h>
#include <cstdint>
#include <cstddef>

// Problem constants
#define BB 4
#define SS 2048
#define EE 1024
#define FF 3072               // 3*EE
#define NTILES 524288         // (SS/2)*(EE/2) tile norms per tensor per batch
#define NROWS 2048            // rows for WO pruning per batch
#define MED_LO 262144         // 1-indexed rank of lower middle (n/2) for n=524288

// ---------------- scratch (device globals; no allocations allowed) ----------------
__device__ float g_qkv[(size_t)BB * SS * FF];        // 96 MB, q|k|v packed per row
__device__ float g_wop[(size_t)BB * SS * EE];        // 32 MB masked WO
__device__ float g_q1[(size_t)BB * SS * SS];         // 64 MB q_
__device__ float g_k1[(size_t)BB * SS * SS];         // 64 MB k_
__device__ float g_pre[(size_t)BB * SS * SS];        // 64 MB precompute
__device__ float g_scl[(size_t)BB * SS * SS];        // 64 MB scale_values
__device__ float g_pro[(size_t)BB * SS * EE];        // 32 MB preoutput
__device__ float g_norm[(size_t)8 * NTILES];         // 16 MB tile norms (tensor = b*2 + {q:0,k:1})
__device__ float g_rownorm[BB * NROWS];
__device__ unsigned g_hist[16][2048];
__device__ unsigned g_prefix[16];
__device__ int g_rank[16];
__device__ float g_selval[16];
__device__ float g_thr[8];
__device__ float g_thro[BB];

// ---------------- helpers ----------------
__device__ __forceinline__ unsigned f2k(float f) {
    unsigned u = __float_as_uint(f);
    return (u & 0x80000000u) ? ~u : (u | 0x80000000u);
}
__device__ __forceinline__ float k2f(unsigned k) {
    unsigned u = (k & 0x80000000u) ? (k & 0x7FFFFFFFu) : ~k;
    return __uint_as_float(u);
}

// ---------------- SGEMM: C = alpha * A (MxK) * op(B) + bias ----------------
// BT=true: B is (N x K) row-major, C += A*B^T (NT). BT=false: B is (K x N) row-major (NN).
template <bool BT, bool BIAS>
__global__ void __launch_bounds__(256, 2) sgemm_kernel(
    const float* __restrict__ A, int lda, size_t sA,
    const float* __restrict__ B, int ldb, size_t sB,
    float* __restrict__ C, int ldc, size_t sC,
    int K, float alpha, const float* __restrict__ bias)
{
    __shared__ float As[2][16][128];
    __shared__ float Bs[2][16][128];

    const int tid = threadIdx.x;
    const int bz = blockIdx.z;
    A += (size_t)bz * sA;
    B += (size_t)bz * sB;
    C += (size_t)bz * sC;

    const int m0 = blockIdx.y * 128;
    const int n0 = blockIdx.x * 128;
    const int tx = tid & 15;
    const int ty = tid >> 4;

    const int ar = tid >> 2;
    const int ac = (tid & 3) * 4;
    const float* Ap0 = A + (size_t)(m0 + ar) * lda + ac;
    const float* Ap1 = A + (size_t)(m0 + ar + 64) * lda + ac;

    const int brr = tid >> 5;
    const int bcc = (tid & 31) * 4;
    const float* Bp0;
    const float* Bp1;
    if (BT) {
        Bp0 = B + (size_t)(n0 + ar) * ldb + ac;
        Bp1 = B + (size_t)(n0 + ar + 64) * ldb + ac;
    } else {
        Bp0 = B + (size_t)brr * ldb + n0 + bcc;
        Bp1 = B + (size_t)(brr + 8) * ldb + n0 + bcc;
    }

    float bj[8];
    if (BIAS) {
#pragma unroll
        for (int j = 0; j < 8; ++j) bj[j] = bias[n0 + tx * 8 + j];
    }

    float acc[8][8] = {};
    float4 ra0, ra1, rb0, rb1;

    ra0 = *(const float4*)(Ap0);
    ra1 = *(const float4*)(Ap1);
    rb0 = *(const float4*)(Bp0);
    rb1 = *(const float4*)(Bp1);
    {
        As[0][ac + 0][ar] = ra0.x; As[0][ac + 1][ar] = ra0.y; As[0][ac + 2][ar] = ra0.z; As[0][ac + 3][ar] = ra0.w;
        As[0][ac + 0][ar + 64] = ra1.x; As[0][ac + 1][ar + 64] = ra1.y; As[0][ac + 2][ar + 64] = ra1.z; As[0][ac + 3][ar + 64] = ra1.w;
        if (BT) {
            Bs[0][ac + 0][ar] = rb0.x; Bs[0][ac + 1][ar] = rb0.y; Bs[0][ac + 2][ar] = rb0.z; Bs[0][ac + 3][ar] = rb0.w;
            Bs[0][ac + 0][ar + 64] = rb1.x; Bs[0][ac + 1][ar + 64] = rb1.y; Bs[0][ac + 2][ar + 64] = rb1.z; Bs[0][ac + 3][ar + 64] = rb1.w;
        } else {
            *(float4*)&Bs[0][brr][bcc] = rb0;
            *(float4*)&Bs[0][brr + 8][bcc] = rb1;
        }
    }
    __syncthreads();

    const int nk = K >> 4;
    for (int t = 0; t < nk; ++t) {
        const int cur = t & 1;
        const int nxt = cur ^ 1;
        if (t + 1 < nk) {
            const int k0 = (t + 1) << 4;
            ra0 = *(const float4*)(Ap0 + k0);
            ra1 = *(const float4*)(Ap1 + k0);
            if (BT) {
                rb0 = *(const float4*)(Bp0 + k0);
                rb1 = *(const float4*)(Bp1 + k0);
            } else {
                rb0 = *(const float4*)(Bp0 + (size_t)k0 * ldb);
                rb1 = *(const float4*)(Bp1 + (size_t)k0 * ldb);
            }
        }
#pragma unroll
        for (int k = 0; k < 16; ++k) {
            float4 a0 = *(const float4*)&As[cur][k][ty * 8];
            float4 a1 = *(const float4*)&As[cur][k][ty * 8 + 4];
            float4 b0 = *(const float4*)&Bs[cur][k][tx * 8];
            float4 b1 = *(const float4*)&Bs[cur][k][tx * 8 + 4];
            float av[8] = {a0.x, a0.y, a0.z, a0.w, a1.x, a1.y, a1.z, a1.w};
            float bv[8] = {b0.x, b0.y, b0.z, b0.w, b1.x, b1.y, b1.z, b1.w};
#pragma unroll
            for (int i = 0; i < 8; ++i)
#pragma unroll
                for (int j = 0; j < 8; ++j)
                    acc[i][j] = fmaf(av[i], bv[j], acc[i][j]);
        }
        if (t + 1 < nk) {
            As[nxt][ac + 0][ar] = ra0.x; As[nxt][ac + 1][ar] = ra0.y; As[nxt][ac + 2][ar] = ra0.z; As[nxt][ac + 3][ar] = ra0.w;
            As[nxt][ac + 0][ar + 64] = ra1.x; As[nxt][ac + 1][ar + 64] = ra1.y; As[nxt][ac + 2][ar + 64] = ra1.z; As[nxt][ac + 3][ar + 64] = ra1.w;
            if (BT) {
                Bs[nxt][ac + 0][ar] = rb0.x; Bs[nxt][ac + 1][ar] = rb0.y; Bs[nxt][ac + 2][ar] = rb0.z; Bs[nxt][ac + 3][ar] = rb0.w;
                Bs[nxt][ac + 0][ar + 64] = rb1.x; Bs[nxt][ac + 1][ar + 64] = rb1.y; Bs[nxt][ac + 2][ar + 64] = rb1.z; Bs[nxt][ac + 3][ar + 64] = rb1.w;
            } else {
                *(float4*)&Bs[nxt][brr][bcc] = rb0;
                *(float4*)&Bs[nxt][brr + 8][bcc] = rb1;
            }
        }
        __syncthreads();
    }

#pragma unroll
    for (int i = 0; i < 8; ++i) {
        float* cp = C + (size_t)(m0 + ty * 8 + i) * ldc + n0 + tx * 8;
        float4 o0, o1;
        o0.x = acc[i][0] * alpha; o0.y = acc[i][1] * alpha; o0.z = acc[i][2] * alpha; o0.w = acc[i][3] * alpha;
        o1.x = acc[i][4] * alpha; o1.y = acc[i][5] * alpha; o1.z = acc[i][6] * alpha; o1.w = acc[i][7] * alpha;
        if (BIAS) {
            o0.x += bj[0]; o0.y += bj[1]; o0.z += bj[2]; o0.w += bj[3];
            o1.x += bj[4]; o1.y += bj[5]; o1.z += bj[6]; o1.w += bj[7];
        }
        *(float4*)cp = o0;
        *((float4*)cp + 1) = o1;
    }
}

// ---------------- high-accuracy tile norms (compensated dot + fp64 norm) ----------------
// For tensor (b, qk): val[s,d] = dot(x[b,s,:], Wqkv[qk*EE+d, :]) with pair-grouped
// twoSum-compensated fp32 accumulation (error ~1e-8 rel). Tile norms in fp64.
// Block: 64(s) x 64(d), 256 threads, 4x4 vals per thread (= 2x2 tiles).
__global__ void __launch_bounds__(256, 2) norm_gemm_kernel(
    const float* __restrict__ x, const float* __restrict__ Wqkv)
{
    __shared__ float Xs[16][64];
    __shared__ float Ws[16][64];

    const int tid = threadIdx.x;
    const int tensor = blockIdx.z;        // b*2 + qk
    const int b = tensor >> 1, qk = tensor & 1;
    const int m0 = blockIdx.y * 64;       // s
    const int n0 = blockIdx.x * 64;       // d
    const int tx = tid & 15;              // d group of 4
    const int ty = tid >> 4;              // s group of 4

    const float* A = x + (size_t)b * SS * EE;
    const float* Bm = Wqkv + (size_t)qk * EE * EE;  // rows d of Wqkv block

    const int lr = tid >> 2;              // 0..63
    const int lc = (tid & 3) * 4;         // k offset
    const float* Ap = A + (size_t)(m0 + lr) * EE + lc;
    const float* Bp = Bm + (size_t)(n0 + lr) * EE + lc;

    float acc[4][4] = {};
    float comp[4][4] = {};

    for (int t = 0; t < EE / 16; ++t) {
        const int k0 = t << 4;
        float4 ra = *(const float4*)(Ap + k0);
        float4 rb = *(const float4*)(Bp + k0);
        Xs[lc + 0][lr] = ra.x; Xs[lc + 1][lr] = ra.y; Xs[lc + 2][lr] = ra.z; Xs[lc + 3][lr] = ra.w;
        Ws[lc + 0][lr] = rb.x; Ws[lc + 1][lr] = rb.y; Ws[lc + 2][lr] = rb.z; Ws[lc + 3][lr] = rb.w;
        __syncthreads();
#pragma unroll
        for (int kk = 0; kk < 8; ++kk) {
            float4 a0 = *(const float4*)&Xs[2 * kk][ty * 4];
            float4 a1 = *(const float4*)&Xs[2 * kk + 1][ty * 4];
            float4 b0 = *(const float4*)&Ws[2 * kk][tx * 4];
            float4 b1 = *(const float4*)&Ws[2 * kk + 1][tx * 4];
            float av0[4] = {a0.x, a0.y, a0.z, a0.w};
            float av1[4] = {a1.x, a1.y, a1.z, a1.w};
            float bv0[4] = {b0.x, b0.y, b0.z, b0.w};
            float bv1[4] = {b1.x, b1.y, b1.z, b1.w};
#pragma unroll
            for (int i = 0; i < 4; ++i)
#pragma unroll
                for (int j = 0; j < 4; ++j) {
                    // pair product with single rounding
                    float p = __fmaf_rn(av1[i], bv1[j], av0[i] * bv0[j]);
                    // twoSum(acc, p)
                    float a = acc[i][j];
                    float s = __fadd_rn(a, p);
                    float z = __fsub_rn(s, a);
                    float e = __fadd_rn(__fsub_rn(a, __fsub_rn(s, z)), __fsub_rn(p, z));
                    acc[i][j] = s;
                    comp[i][j] = __fadd_rn(comp[i][j], e);
                }
        }
        __syncthreads();
    }

    // exact-ish values in double, then 2x2 tile norms in double
    double v[4][4];
#pragma unroll
    for (int i = 0; i < 4; ++i)
#pragma unroll
        for (int j = 0; j < 4; ++j)
            v[i][j] = (double)acc[i][j] + (double)comp[i][j];

    float* np = g_norm + (size_t)tensor * NTILES;
#pragma unroll
    for (int ti = 0; ti < 2; ++ti)
#pragma unroll
        for (int tj = 0; tj < 2; ++tj) {
            double s = v[2 * ti][2 * tj] * v[2 * ti][2 * tj]
                     + v[2 * ti][2 * tj + 1] * v[2 * ti][2 * tj + 1]
                     + v[2 * ti + 1][2 * tj] * v[2 * ti + 1][2 * tj]
                     + v[2 * ti + 1][2 * tj + 1] * v[2 * ti + 1][2 * tj + 1];
            int ts = (m0 + ty * 4) / 2 + ti;
            int td = (n0 + tx * 4) / 2 + tj;
            np[(size_t)ts * 512 + td] = (float)sqrt(s);
        }
}

// ---------------- radix select (exact medians over 524288 per tensor) ----------------
__global__ void sel_init_kernel() {
    int tid = blockIdx.x * blockDim.x + threadIdx.x;
    unsigned* h = &g_hist[0][0];
    for (int i = tid; i < 16 * 2048; i += gridDim.x * blockDim.x) h[i] = 0;
    if (tid < 16) {
        g_prefix[tid] = 0;
        g_rank[tid] = MED_LO + (tid & 1);
    }
}

__global__ void hist_kernel(int shift, unsigned pmask, int bins) {
    __shared__ unsigned h0[2048];
    __shared__ unsigned h1[2048];
    const int tensor = blockIdx.y;
    for (int i = threadIdx.x; i < bins; i += blockDim.x) { h0[i] = 0; h1[i] = 0; }
    __syncthreads();
    const int s0 = tensor * 2, s1 = s0 + 1;
    const unsigned p0 = g_prefix[s0], p1 = g_prefix[s1];
    const float* base = g_norm + (size_t)tensor * NTILES;
    const unsigned bm = (unsigned)bins - 1u;
    for (unsigned i = blockIdx.x * blockDim.x + threadIdx.x; i < NTILES; i += gridDim.x * blockDim.x) {
        unsigned key = f2k(base[i]);
        unsigned bin = (key >> shift) & bm;
        if ((key & pmask) == p0) atomicAdd(&h0[bin], 1u);
        if ((key & pmask) == p1) atomicAdd(&h1[bin], 1u);
    }
    __syncthreads();
    for (int i = threadIdx.x; i < bins; i += blockDim.x) {
        if (h0[i]) atomicAdd(&g_hist[s0][i], h0[i]);
        if (h1[i]) atomicAdd(&g_hist[s1][i], h1[i]);
    }
}

__global__ void pick_kernel(int shift, int bins) {
    __shared__ unsigned h[2048];
    __shared__ unsigned csum[257];
    const int s = blockIdx.x;
    const int tid = threadIdx.x;
    for (int i = tid; i < bins; i += 256) h[i] = g_hist[s][i];
    for (int i = tid; i < 2048; i += 256) g_hist[s][i] = 0;
    __syncthreads();
    const int cpt = bins / 256;
    unsigned ssum = 0;
    for (int i = 0; i < cpt; ++i) ssum += h[tid * cpt + i];
    csum[tid] = ssum;
    __syncthreads();
    if (tid == 0) {
        unsigned acc = 0;
        for (int i = 0; i < 256; ++i) { unsigned v = csum[i]; csum[i] = acc; acc += v; }
        csum[256] = acc;
        int rank = g_rank[s];
        int c = 0;
        while (c < 255 && (int)csum[c + 1] < rank) ++c;
        unsigned accb = csum[c];
        int b = c * cpt;
        while ((int)(accb + h[b]) < rank) { accb += h[b]; ++b; }
        g_rank[s] = rank - (int)accb;
        g_prefix[s] |= ((unsigned)b << shift);
        if (shift == 0) g_selval[s] = k2f(g_prefix[s]);
    }
}

__global__ void thr_kernel() {
    int t = threadIdx.x;
    if (t < 8) g_thr[t] = 0.5f * (g_selval[2 * t] + g_selval[2 * t + 1]);
}

// ---------------- WO row pruning (fp64 accumulation) ----------------
__global__ void row_norm_kernel(const float* __restrict__ WO) {
    int row = blockIdx.x * 8 + (threadIdx.x >> 5);
    int lane = threadIdx.x & 31;
    const float* p = WO + (size_t)row * EE;
    double s = 0.0;
    for (int i = lane; i < EE; i += 32) { double v = (double)p[i]; s += v * v; }
#pragma unroll
    for (int o = 16; o; o >>= 1) s += __shfl_xor_sync(0xFFFFFFFFu, s, o);
    if (lane == 0) g_rownorm[row] = (float)sqrt(s);
}

__global__ void median_rows_kernel() {
    __shared__ float v[2048];
    const int b = blockIdx.x;
    const int tid = threadIdx.x;
    v[tid] = g_rownorm[b * NROWS + tid];
    v[tid + 1024] = g_rownorm[b * NROWS + tid + 1024];
    __syncthreads();
    for (int k = 2; k <= 2048; k <<= 1) {
        for (int j = k >> 1; j > 0; j >>= 1) {
#pragma unroll
            for (int m = 0; m < 2; ++m) {
                int i = tid + m * 1024;
                int ixj = i ^ j;
                if (ixj > i) {
                    bool up = (i & k) == 0;
                    float a = v[i], c = v[ixj];
                    if ((a > c) == up) { v[i] = c; v[ixj] = a; }
                }
            }
            __syncthreads();
        }
    }
    if (tid == 0) g_thro[b] = 0.5f * (v[1023] + v[1024]);
}

// ---------------- apply masks ----------------
__global__ void mask_qk_kernel() {
    size_t idx = (size_t)blockIdx.x * blockDim.x + threadIdx.x;
    if (idx >= (size_t)BB * SS * 2048) return;
    int f = (int)(idx & 2047);
    int s = (int)((idx >> 11) & (SS - 1));
    int b = (int)(idx >> 22);
    int qk = f >> 10, d = f & 1023;
    int t = b * 2 + qk;
    float nm = g_norm[(size_t)t * NTILES + (size_t)(s >> 1) * 512 + (d >> 1)];
    if (!(nm >= g_thr[t])) g_qkv[((size_t)b * SS + s) * FF + f] = 0.f;
}

__global__ void mask_wo_kernel(const float* __restrict__ WO) {
    size_t idx = (size_t)blockIdx.x * blockDim.x + threadIdx.x;
    if (idx >= (size_t)BB * SS * EE) return;
    int row = (int)(idx >> 10);
    int b = row >> 11;
    float keep = (g_rownorm[row] >= g_thro[b]) ? 1.f : 0.f;
    g_wop[idx] = WO[idx] * keep;
}

// ---------------- host launch ----------------
static void* sym_addr(const void* s) {
    void* p = nullptr;
    cudaGetSymbolAddress(&p, s);
    return p;
}

extern "C" void kernel_launch(void* const* d_in, const int* in_sizes, int n_in,
                              void* d_out, int out_size) {
    const float* x    = (const float*)d_in[0];
    const float* Wqkv = (const float*)d_in[1];
    const float* bqkv = (const float*)d_in[2];
    const float* WO   = (const float*)d_in[3];
    float* out = (float*)d_out;

    float* qkv  = (float*)sym_addr(g_qkv);
    float* wop  = (float*)sym_addr(g_wop);
    float* q1   = (float*)sym_addr(g_q1);
    float* k1   = (float*)sym_addr(g_k1);
    float* pre  = (float*)sym_addr(g_pre);
    float* scl  = (float*)sym_addr(g_scl);
    float* pro  = (float*)sym_addr(g_pro);

    const size_t sXE = (size_t)SS * EE;
    const size_t sQK = (size_t)SS * FF;
    const size_t sSQ = (size_t)SS * SS;

    // 1) qkv = x @ Wqkv^T + bqkv   (NT, shared B across batch)
    sgemm_kernel<true, true><<<dim3(FF / 128, SS / 128, BB), 256>>>(
        x, EE, sXE, Wqkv, EE, 0, qkv, FF, sQK, EE, 1.0f, bqkv);

    // 2) high-accuracy tile norms of q,k (compensated dot, fp64 norms)
    norm_gemm_kernel<<<dim3(16, 32, 8), 256>>>(x, Wqkv);

    // 3) WO row norms (fp64 accumulation)
    row_norm_kernel<<<(BB * NROWS) / 8, 256>>>(WO);

    // 4) exact medians of tile norms via 3-pass radix select (11+11+10 bits)
    sel_init_kernel<<<32, 256>>>();
    hist_kernel<<<dim3(32, 8), 256>>>(21, 0x00000000u, 2048);
    pick_kernel<<<16, 256>>>(21, 2048);
    hist_kernel<<<dim3(32, 8), 256>>>(10, 0xFFE00000u, 2048);
    pick_kernel<<<16, 256>>>(10, 2048);
    hist_kernel<<<dim3(32, 8), 256>>>(0, 0xFFFFFC00u, 1024);
    pick_kernel<<<16, 256>>>(0, 1024);
    thr_kernel<<<1, 32>>>();

    // 5) exact median of row norms (bitonic sort, n=2048 per batch)
    median_rows_kernel<<<BB, 1024>>>();

    // 6) apply masks
    mask_qk_kernel<<<((size_t)BB * SS * 2048) / 256, 256>>>();
    mask_wo_kernel<<<((size_t)BB * SS * EE) / 256, 256>>>(WO);

    // 7) q_ = x @ qp^T ; k_ = x @ kp^T ; pre = v @ WOp^T   (NT, K=1024)
    sgemm_kernel<true, false><<<dim3(SS / 128, SS / 128, BB), 256>>>(
        x, EE, sXE, qkv + 0, FF, sQK, q1, SS, sSQ, EE, 1.0f, nullptr);
    sgemm_kernel<true, false><<<dim3(SS / 128, SS / 128, BB), 256>>>(
        x, EE, sXE, qkv + EE, FF, sQK, k1, SS, sSQ, EE, 1.0f, nullptr);
    sgemm_kernel<true, false><<<dim3(SS / 128, SS / 128, BB), 256>>>(
        qkv + 2 * EE, FF, sQK, wop, EE, sXE, pre, SS, sSQ, EE, 1.0f, nullptr);

    // 8) scale = (q_ @ k_^T) * (1/32)   (NT, K=2048; /32 exact, power of 2)
    sgemm_kernel<true, false><<<dim3(SS / 128, SS / 128, BB), 256>>>(
        q1, SS, sSQ, k1, SS, sSQ, scl, SS, sSQ, SS, 0.03125f, nullptr);

    // 9) preout = pre @ x   (NN, K=2048)
    sgemm_kernel<false, false><<<dim3(EE / 128, SS / 128, BB), 256>>>(
        pre, SS, sSQ, x, EE, sXE, pro, EE, sXE, SS, 1.0f, nullptr);

    // 10) out = scale @ preout   (NN, K=2048)
    sgemm_kernel<false, false><<<dim3(EE / 128, SS / 128, BB), 256>>>(
        scl, SS, sSQ, pro, EE, sXE, out, EE, sXE, SS, 1.0f, nullptr);
}

// round 6
// speedup vs baseline: 1.6648x; 1.6648x over previous
#include <cuda_runtime.h>
#include <cuda_bf16.h>
#include <cstdint>
#include <cstddef>

// Problem constants
#define BB 4
#define SS 2048
#define EE 1024
#define NTILES 524288         // (SS/2)*(EE/2) tile norms per tensor per batch
#define NROWS 2048
#define MED_LO 262144

static constexpr size_t XPL  = (size_t)BB * SS * EE;   // 8M elems
static constexpr size_t SQPL = (size_t)BB * SS * SS;   // 16M elems
static constexpr size_t WPL  = (size_t)EE * EE;        // 1M elems

// ---------------- scratch (device globals; no allocations allowed) ----------------
__device__ float g_qk[(size_t)BB * SS * 2048];        // exact q|k values (bias incl.)
__device__ float g_norm[(size_t)8 * NTILES];
__device__ float g_rownorm[BB * NROWS];
__device__ unsigned g_hist[16][2048];
__device__ unsigned g_prefix[16];
__device__ int g_rank[16];
__device__ float g_selval[16];
__device__ float g_thr[8];
__device__ float g_thro[BB];

// bf16 split-2 planes (plane stride = logical tensor size)
__device__ __align__(128) __nv_bfloat16 g_xs  [2 * XPL];
__device__ __align__(128) __nv_bfloat16 g_xts [2 * XPL];
__device__ __align__(128) __nv_bfloat16 g_wvs [2 * WPL];
__device__ __align__(128) __nv_bfloat16 g_qs  [2 * XPL];
__device__ __align__(128) __nv_bfloat16 g_ks  [2 * XPL];
__device__ __align__(128) __nv_bfloat16 g_vs  [2 * XPL];
__device__ __align__(128) __nv_bfloat16 g_wos [2 * XPL];
__device__ __align__(128) __nv_bfloat16 g_q1s [2 * SQPL];
__device__ __align__(128) __nv_bfloat16 g_k1s [2 * SQPL];
__device__ __align__(128) __nv_bfloat16 g_pres[2 * SQPL];
__device__ __align__(128) __nv_bfloat16 g_scls[2 * SQPL];
__device__ __align__(128) __nv_bfloat16 g_pts [2 * XPL];   // preoutput^T splits

// ---------------- small helpers ----------------
__device__ __forceinline__ unsigned f2k(float f) {
    unsigned u = __float_as_uint(f);
    return (u & 0x80000000u) ? ~u : (u | 0x80000000u);
}
__device__ __forceinline__ float k2f(unsigned k) {
    unsigned u = (k & 0x80000000u) ? (k & 0x7FFFFFFFu) : ~k;
    return __uint_as_float(u);
}
__device__ __forceinline__ void split2(float v, __nv_bfloat16& a, __nv_bfloat16& b) {
    a = __float2bfloat16_rn(v);
    b = __float2bfloat16_rn(v - __bfloat162float(a));
}
__device__ __forceinline__ uint32_t packbf2(__nv_bfloat16 lo, __nv_bfloat16 hi) {
    return ((uint32_t)__bfloat16_as_ushort(hi) << 16) | __bfloat16_as_ushort(lo);
}

// ---------------- mma.sync bf16 (sm_80+; works on baseline sm_100) ----------------
__device__ __forceinline__ void mma16816(float* c, const uint32_t* a, const uint32_t* b) {
    asm volatile("mma.sync.aligned.m16n8k16.row.col.f32.bf16.bf16.f32 "
                 "{%0,%1,%2,%3}, {%4,%5,%6,%7}, {%8,%9}, {%0,%1,%2,%3};\n"
                 : "+f"(c[0]), "+f"(c[1]), "+f"(c[2]), "+f"(c[3])
                 : "r"(a[0]), "r"(a[1]), "r"(a[2]), "r"(a[3]), "r"(b[0]), "r"(b[1]));
}

// ---------------- split-2 bf16 NT GEMM on mma.sync ----------------
// D[m,n] = alpha * sum_k A[m,k]*B[n,k] (+bias[n]); A,B as 2 bf16 planes (hi,lo).
// Emulated fp32 via hi*hi + hi*lo + lo*hi. CTA tile 128x128, K-step 32, 8 warps.
#define PK 40                                   // padded smem row (elements)
static constexpr int PLANE_ELEMS = 128 * PK;    // one 128x32 tile (padded)
static constexpr int SMEM_BYTES = 8 * PLANE_ELEMS * 2;   // 2buf*2planes*(A+B) = 81920

template <bool OUTF32, bool BIAS>
__global__ void __launch_bounds__(256) gemm2_kernel(
    const __nv_bfloat16* __restrict__ A, size_t aPlane, size_t aBatch,
    const __nv_bfloat16* __restrict__ Bm, size_t bPlane, size_t bBatch,
    __nv_bfloat16* __restrict__ Osp, size_t oPlane, size_t oBatch,
    float* __restrict__ Cf, size_t cBatch,
    int N, int K, float alpha, const float* __restrict__ bias)
{
    extern __shared__ __align__(16) char smraw[];
    __nv_bfloat16* sm = (__nv_bfloat16*)smraw;
    // layout: A tiles at (buf*2+plane)*PLANE_ELEMS; B tiles at +4*PLANE_ELEMS

    const int tid = threadIdx.x;
    const int wid = tid >> 5, lane = tid & 31;
    const int bz = blockIdx.z;
    const int m0 = blockIdx.y * 128, n0 = blockIdx.x * 128;
    const int wm = (wid & 1) * 64, wn = (wid >> 1) * 32;

    A  += (size_t)bz * aBatch + (size_t)m0 * K;
    Bm += (size_t)bz * bBatch + (size_t)n0 * K;

    const int lr = tid >> 2;           // loader row 0..63 (also +64)
    const int lq = (tid & 3) * 8;      // loader k offset (8 bf16 = uint4)

    float acc[4][4][4];
#pragma unroll
    for (int i = 0; i < 4; ++i)
#pragma unroll
        for (int j = 0; j < 4; ++j)
#pragma unroll
            for (int t = 0; t < 4; ++t) acc[i][j][t] = 0.f;

    // prologue: chunk 0 straight to smem buffer 0
#pragma unroll
    for (int p = 0; p < 2; ++p) {
        __nv_bfloat16* dA = sm + p * PLANE_ELEMS;
        __nv_bfloat16* dB = sm + 4 * PLANE_ELEMS + p * PLANE_ELEMS;
        *(uint4*)(dA + lr * PK + lq)        = *(const uint4*)(A + p * aPlane + (size_t)lr * K + lq);
        *(uint4*)(dA + (lr + 64) * PK + lq) = *(const uint4*)(A + p * aPlane + (size_t)(lr + 64) * K + lq);
        *(uint4*)(dB + lr * PK + lq)        = *(const uint4*)(Bm + p * bPlane + (size_t)lr * K + lq);
        *(uint4*)(dB + (lr + 64) * PK + lq) = *(const uint4*)(Bm + p * bPlane + (size_t)(lr + 64) * K + lq);
    }
    __syncthreads();

    const int nk = K >> 5;
    for (int c = 0; c < nk; ++c) {
        const int cur = c & 1, nxt = cur ^ 1;
        uint4 ra[2][2], rb[2][2];
        if (c + 1 < nk) {
            const int k0 = (c + 1) << 5;
#pragma unroll
            for (int p = 0; p < 2; ++p) {
                ra[p][0] = *(const uint4*)(A + p * aPlane + (size_t)lr * K + k0 + lq);
                ra[p][1] = *(const uint4*)(A + p * aPlane + (size_t)(lr + 64) * K + k0 + lq);
                rb[p][0] = *(const uint4*)(Bm + p * bPlane + (size_t)lr * K + k0 + lq);
                rb[p][1] = *(const uint4*)(Bm + p * bPlane + (size_t)(lr + 64) * K + k0 + lq);
            }
        }

        const __nv_bfloat16* sA0 = sm + (cur * 2 + 0) * PLANE_ELEMS;
        const __nv_bfloat16* sA1 = sm + (cur * 2 + 1) * PLANE_ELEMS;
        const __nv_bfloat16* sB0 = sm + 4 * PLANE_ELEMS + (cur * 2 + 0) * PLANE_ELEMS;
        const __nv_bfloat16* sB1 = sm + 4 * PLANE_ELEMS + (cur * 2 + 1) * PLANE_ELEMS;

#pragma unroll
        for (int kb = 0; kb < 32; kb += 16) {
            const int kq = kb + (lane & 3) * 2;
            // B fragments: 2 planes x 4 n-tiles x 2 regs
            uint32_t bf[2][4][2];
#pragma unroll
            for (int nt = 0; nt < 4; ++nt) {
                const int br = wn + nt * 8 + (lane >> 2);
                bf[0][nt][0] = *(const uint32_t*)(sB0 + br * PK + kq);
                bf[0][nt][1] = *(const uint32_t*)(sB0 + br * PK + kq + 8);
                bf[1][nt][0] = *(const uint32_t*)(sB1 + br * PK + kq);
                bf[1][nt][1] = *(const uint32_t*)(sB1 + br * PK + kq + 8);
            }
#pragma unroll
            for (int mt = 0; mt < 4; ++mt) {
                const int ar = wm + mt * 16 + (lane >> 2);
                uint32_t af[2][4];
#pragma unroll
                for (int p = 0; p < 2; ++p) {
                    const __nv_bfloat16* sA = p ? sA1 : sA0;
                    af[p][0] = *(const uint32_t*)(sA + ar * PK + kq);
                    af[p][1] = *(const uint32_t*)(sA + (ar + 8) * PK + kq);
                    af[p][2] = *(const uint32_t*)(sA + ar * PK + kq + 8);
                    af[p][3] = *(const uint32_t*)(sA + (ar + 8) * PK + kq + 8);
                }
#pragma unroll
                for (int nt = 0; nt < 4; ++nt) {
                    mma16816(acc[mt][nt], af[0], bf[0][nt]);  // hi*hi
                    mma16816(acc[mt][nt], af[0], bf[1][nt]);  // hi*lo
                    mma16816(acc[mt][nt], af[1], bf[0][nt]);  // lo*hi
                }
            }
        }

        if (c + 1 < nk) {
#pragma unroll
            for (int p = 0; p < 2; ++p) {
                __nv_bfloat16* dA = sm + (nxt * 2 + p) * PLANE_ELEMS;
                __nv_bfloat16* dB = sm + 4 * PLANE_ELEMS + (nxt * 2 + p) * PLANE_ELEMS;
                *(uint4*)(dA + lr * PK + lq)        = ra[p][0];
                *(uint4*)(dA + (lr + 64) * PK + lq) = ra[p][1];
                *(uint4*)(dB + lr * PK + lq)        = rb[p][0];
                *(uint4*)(dB + (lr + 64) * PK + lq) = rb[p][1];
            }
        }
        __syncthreads();
    }

    // epilogue
#pragma unroll
    for (int mt = 0; mt < 4; ++mt) {
#pragma unroll
        for (int nt = 0; nt < 4; ++nt) {
            const int r0 = m0 + wm + mt * 16 + (lane >> 2);
            const int cc = n0 + wn + nt * 8 + (lane & 3) * 2;
            float v00 = acc[mt][nt][0] * alpha, v01 = acc[mt][nt][1] * alpha;
            float v10 = acc[mt][nt][2] * alpha, v11 = acc[mt][nt][3] * alpha;
            if (BIAS) {
                const float b0 = bias[cc], b1 = bias[cc + 1];
                v00 += b0; v01 += b1; v10 += b0; v11 += b1;
            }
            if (OUTF32) {
                float* base = Cf + (size_t)bz * cBatch;
                *(float2*)(base + (size_t)r0 * N + cc)       = make_float2(v00, v01);
                *(float2*)(base + (size_t)(r0 + 8) * N + cc) = make_float2(v10, v11);
            } else {
                __nv_bfloat16 h00, l00, h01, l01, h10, l10, h11, l11;
                split2(v00, h00, l00); split2(v01, h01, l01);
                split2(v10, h10, l10); split2(v11, h11, l11);
                size_t b0 = (size_t)bz * oBatch + (size_t)r0 * N + cc;
                size_t b1 = (size_t)bz * oBatch + (size_t)(r0 + 8) * N + cc;
                *(uint32_t*)(Osp + b0)          = packbf2(h00, h01);
                *(uint32_t*)(Osp + b1)          = packbf2(h10, h11);
                *(uint32_t*)(Osp + oPlane + b0) = packbf2(l00, l01);
                *(uint32_t*)(Osp + oPlane + b1) = packbf2(l10, l11);
            }
        }
    }
}

// ---------------- exact tile norms + q,k values (compensated dot + fp64) ----------------
__global__ void __launch_bounds__(256, 2) norm_gemm_kernel(
    const float* __restrict__ x, const float* __restrict__ Wqkv, const float* __restrict__ bqkv)
{
    __shared__ float Xs[16][64];
    __shared__ float Ws[16][64];

    const int tid = threadIdx.x;
    const int tensor = blockIdx.z;        // b*2 + qk
    const int b = tensor >> 1, qk = tensor & 1;
    const int m0 = blockIdx.y * 64;
    const int n0 = blockIdx.x * 64;
    const int tx = tid & 15;
    const int ty = tid >> 4;

    const float* A = x + (size_t)b * SS * EE;
    const float* Bm = Wqkv + (size_t)qk * EE * EE;

    const int lr = tid >> 2;
    const int lc = (tid & 3) * 4;
    const float* Ap = A + (size_t)(m0 + lr) * EE + lc;
    const float* Bp = Bm + (size_t)(n0 + lr) * EE + lc;

    float acc[4][4] = {};
    float comp[4][4] = {};

    for (int t = 0; t < EE / 16; ++t) {
        const int k0 = t << 4;
        float4 ra = *(const float4*)(Ap + k0);
        float4 rb = *(const float4*)(Bp + k0);
        Xs[lc + 0][lr] = ra.x; Xs[lc + 1][lr] = ra.y; Xs[lc + 2][lr] = ra.z; Xs[lc + 3][lr] = ra.w;
        Ws[lc + 0][lr] = rb.x; Ws[lc + 1][lr] = rb.y; Ws[lc + 2][lr] = rb.z; Ws[lc + 3][lr] = rb.w;
        __syncthreads();
#pragma unroll
        for (int kk = 0; kk < 8; ++kk) {
            float4 a0 = *(const float4*)&Xs[2 * kk][ty * 4];
            float4 a1 = *(const float4*)&Xs[2 * kk + 1][ty * 4];
            float4 b0 = *(const float4*)&Ws[2 * kk][tx * 4];
            float4 b1 = *(const float4*)&Ws[2 * kk + 1][tx * 4];
            float av0[4] = {a0.x, a0.y, a0.z, a0.w};
            float av1[4] = {a1.x, a1.y, a1.z, a1.w};
            float bv0[4] = {b0.x, b0.y, b0.z, b0.w};
            float bv1[4] = {b1.x, b1.y, b1.z, b1.w};
#pragma unroll
            for (int i = 0; i < 4; ++i)
#pragma unroll
                for (int j = 0; j < 4; ++j) {
                    float p = __fmaf_rn(av1[i], bv1[j], av0[i] * bv0[j]);
                    float a = acc[i][j];
                    float s = __fadd_rn(a, p);
                    float z = __fsub_rn(s, a);
                    float e = __fadd_rn(__fsub_rn(a, __fsub_rn(s, z)), __fsub_rn(p, z));
                    acc[i][j] = s;
                    comp[i][j] = __fadd_rn(comp[i][j], e);
                }
        }
        __syncthreads();
    }

    double v[4][4];
#pragma unroll
    for (int i = 0; i < 4; ++i)
#pragma unroll
        for (int j = 0; j < 4; ++j) {
            double bj = (double)bqkv[(size_t)qk * EE + n0 + tx * 4 + j];
            v[i][j] = (double)acc[i][j] + (double)comp[i][j] + bj;
            int s = m0 + ty * 4 + i;
            int d = n0 + tx * 4 + j;
            g_qk[((size_t)(b * SS + s)) * 2048 + qk * 1024 + d] = (float)v[i][j];
        }

    float* np = g_norm + (size_t)tensor * NTILES;
#pragma unroll
    for (int ti = 0; ti < 2; ++ti)
#pragma unroll
        for (int tj = 0; tj < 2; ++tj) {
            double s = v[2 * ti][2 * tj] * v[2 * ti][2 * tj]
                     + v[2 * ti][2 * tj + 1] * v[2 * ti][2 * tj + 1]
                     + v[2 * ti + 1][2 * tj] * v[2 * ti + 1][2 * tj]
                     + v[2 * ti + 1][2 * tj + 1] * v[2 * ti + 1][2 * tj + 1];
            int ts = (m0 + ty * 4) / 2 + ti;
            int td = (n0 + tx * 4) / 2 + tj;
            np[(size_t)ts * 512 + td] = (float)sqrt(s);
        }
}

// ---------------- radix select (exact medians) ----------------
__global__ void sel_init_kernel() {
    int tid = blockIdx.x * blockDim.x + threadIdx.x;
    unsigned* h = &g_hist[0][0];
    for (int i = tid; i < 16 * 2048; i += gridDim.x * blockDim.x) h[i] = 0;
    if (tid < 16) { g_prefix[tid] = 0; g_rank[tid] = MED_LO + (tid & 1); }
}

__global__ void hist_kernel(int shift, unsigned pmask, int bins) {
    __shared__ unsigned h0[2048];
    __shared__ unsigned h1[2048];
    const int tensor = blockIdx.y;
    for (int i = threadIdx.x; i < bins; i += blockDim.x) { h0[i] = 0; h1[i] = 0; }
    __syncthreads();
    const int s0 = tensor * 2, s1 = s0 + 1;
    const unsigned p0 = g_prefix[s0], p1 = g_prefix[s1];
    const float* base = g_norm + (size_t)tensor * NTILES;
    const unsigned bm = (unsigned)bins - 1u;
    for (unsigned i = blockIdx.x * blockDim.x + threadIdx.x; i < NTILES; i += gridDim.x * blockDim.x) {
        unsigned key = f2k(base[i]);
        unsigned bin = (key >> shift) & bm;
        if ((key & pmask) == p0) atomicAdd(&h0[bin], 1u);
        if ((key & pmask) == p1) atomicAdd(&h1[bin], 1u);
    }
    __syncthreads();
    for (int i = threadIdx.x; i < bins; i += blockDim.x) {
        if (h0[i]) atomicAdd(&g_hist[s0][i], h0[i]);
        if (h1[i]) atomicAdd(&g_hist[s1][i], h1[i]);
    }
}

__global__ void pick_kernel(int shift, int bins) {
    __shared__ unsigned h[2048];
    __shared__ unsigned csum[257];
    const int s = blockIdx.x;
    const int tid = threadIdx.x;
    for (int i = tid; i < bins; i += 256) h[i] = g_hist[s][i];
    for (int i = tid; i < 2048; i += 256) g_hist[s][i] = 0;
    __syncthreads();
    const int cpt = bins / 256;
    unsigned ssum = 0;
    for (int i = 0; i < cpt; ++i) ssum += h[tid * cpt + i];
    csum[tid] = ssum;
    __syncthreads();
    if (tid == 0) {
        unsigned acc = 0;
        for (int i = 0; i < 256; ++i) { unsigned v = csum[i]; csum[i] = acc; acc += v; }
        csum[256] = acc;
        int rank = g_rank[s];
        int c = 0;
        while (c < 255 && (int)csum[c + 1] < rank) ++c;
        unsigned accb = csum[c];
        int b = c * cpt;
        while ((int)(accb + h[b]) < rank) { accb += h[b]; ++b; }
        g_rank[s] = rank - (int)accb;
        g_prefix[s] |= ((unsigned)b << shift);
        if (shift == 0) g_selval[s] = k2f(g_prefix[s]);
    }
}

__global__ void thr_kernel() {
    int t = threadIdx.x;
    if (t < 8) g_thr[t] = 0.5f * (g_selval[2 * t] + g_selval[2 * t + 1]);
}

// ---------------- WO row pruning ----------------
__global__ void row_norm_kernel(const float* __restrict__ WO) {
    int row = blockIdx.x * 8 + (threadIdx.x >> 5);
    int lane = threadIdx.x & 31;
    const float* p = WO + (size_t)row * EE;
    double s = 0.0;
    for (int i = lane; i < EE; i += 32) { double v = (double)p[i]; s += v * v; }
#pragma unroll
    for (int o = 16; o; o >>= 1) s += __shfl_xor_sync(0xFFFFFFFFu, s, o);
    if (lane == 0) g_rownorm[row] = (float)sqrt(s);
}

__global__ void median_rows_kernel() {
    __shared__ float v[2048];
    const int b = blockIdx.x;
    const int tid = threadIdx.x;
    v[tid] = g_rownorm[b * NROWS + tid];
    v[tid + 1024] = g_rownorm[b * NROWS + tid + 1024];
    __syncthreads();
    for (int k = 2; k <= 2048; k <<= 1) {
        for (int j = k >> 1; j > 0; j >>= 1) {
#pragma unroll
            for (int m = 0; m < 2; ++m) {
                int i = tid + m * 1024;
                int ixj = i ^ j;
                if (ixj > i) {
                    bool up = (i & k) == 0;
                    float a = v[i], c = v[ixj];
                    if ((a > c) == up) { v[i] = c; v[ixj] = a; }
                }
            }
            __syncthreads();
        }
    }
    if (tid == 0) g_thro[b] = 0.5f * (v[1023] + v[1024]);
}

// ---------------- split / transpose / mask kernels ----------------
__global__ void split_x_kernel(const float* __restrict__ x) {
    __shared__ float t[32][33];
    const int b = blockIdx.z;
    const int i0 = blockIdx.y * 32;   // S
    const int j0 = blockIdx.x * 32;   // E
    const int lj = threadIdx.x;       // 32
    const int li = threadIdx.y;       // 8
    const float* xb = x + (size_t)b * SS * EE;
    for (int r = li; r < 32; r += 8) {
        float v = xb[(size_t)(i0 + r) * EE + j0 + lj];
        t[r][lj] = v;
        __nv_bfloat16 a, bb;
        split2(v, a, bb);
        size_t o = (size_t)b * SS * EE + (size_t)(i0 + r) * EE + j0 + lj;
        g_xs[o] = a; g_xs[XPL + o] = bb;
    }
    __syncthreads();
    for (int r = li; r < 32; r += 8) {
        float v = t[lj][r];
        __nv_bfloat16 a, bb;
        split2(v, a, bb);
        size_t o = (size_t)b * EE * SS + (size_t)(j0 + r) * SS + i0 + lj;
        g_xts[o] = a; g_xts[XPL + o] = bb;
    }
}

__global__ void split_wv_kernel(const float* __restrict__ Wqkv) {
    size_t idx = (size_t)blockIdx.x * blockDim.x + threadIdx.x;   // over EE*EE
    if (idx >= WPL) return;
    float v = Wqkv[(size_t)2 * EE * EE + idx];
    __nv_bfloat16 a, b;
    split2(v, a, b);
    g_wvs[idx] = a; g_wvs[WPL + idx] = b;
}

__global__ void mask_split_qk_kernel() {
    size_t idx = (size_t)blockIdx.x * blockDim.x + threadIdx.x;   // over BB*SS*2048
    if (idx >= (size_t)BB * SS * 2048) return;
    int col = (int)(idx & 2047);
    int s = (int)((idx >> 11) & (SS - 1));
    int b = (int)(idx >> 22);
    int qk = col >> 10, d = col & 1023;
    int t = b * 2 + qk;
    float v = g_qk[idx];
    float nm = g_norm[(size_t)t * NTILES + (size_t)(s >> 1) * 512 + (d >> 1)];
    if (!(nm >= g_thr[t])) v = 0.f;
    __nv_bfloat16 a, bb;
    split2(v, a, bb);
    size_t o = (size_t)b * SS * EE + (size_t)s * EE + d;
    __nv_bfloat16* dst = qk ? g_ks : g_qs;
    dst[o] = a; dst[XPL + o] = bb;
}

__global__ void mask_split_wo_kernel(const float* __restrict__ WO) {
    size_t idx = (size_t)blockIdx.x * blockDim.x + threadIdx.x;   // over BB*SS*EE
    if (idx >= (size_t)BB * SS * EE) return;
    int row = (int)(idx >> 10);
    int b = row >> 11;
    float v = (g_rownorm[row] >= g_thro[b]) ? WO[idx] : 0.f;
    __nv_bfloat16 a, bb;
    split2(v, a, bb);
    g_wos[idx] = a; g_wos[XPL + idx] = bb;
}

// ---------------- host launch ----------------
extern "C" void kernel_launch(void* const* d_in, const int* in_sizes, int n_in,
                              void* d_out, int out_size) {
    const float* x    = (const float*)d_in[0];
    const float* Wqkv = (const float*)d_in[1];
    const float* bqkv = (const float*)d_in[2];
    const float* WO   = (const float*)d_in[3];
    float* out = (float*)d_out;

    cudaFuncSetAttribute(gemm2_kernel<false, false>, cudaFuncAttributeMaxDynamicSharedMemorySize, SMEM_BYTES);
    cudaFuncSetAttribute(gemm2_kernel<false, true>,  cudaFuncAttributeMaxDynamicSharedMemorySize, SMEM_BYTES);
    cudaFuncSetAttribute(gemm2_kernel<true, false>,  cudaFuncAttributeMaxDynamicSharedMemorySize, SMEM_BYTES);

    const size_t sXE = (size_t)SS * EE;      // per-batch stride, (S,E)-shaped tensors
    const size_t sES = (size_t)EE * SS;      // per-batch stride, (E,S)-shaped (xT, proT)
    const size_t sSQ = (size_t)SS * SS;

    __nv_bfloat16 *xs, *xts, *wvs, *qs, *ks, *vs, *wos, *q1s, *k1s, *pres, *scls, *pts;
    cudaGetSymbolAddress((void**)&xs, g_xs);
    cudaGetSymbolAddress((void**)&xts, g_xts);
    cudaGetSymbolAddress((void**)&wvs, g_wvs);
    cudaGetSymbolAddress((void**)&qs, g_qs);
    cudaGetSymbolAddress((void**)&ks, g_ks);
    cudaGetSymbolAddress((void**)&vs, g_vs);
    cudaGetSymbolAddress((void**)&wos, g_wos);
    cudaGetSymbolAddress((void**)&q1s, g_q1s);
    cudaGetSymbolAddress((void**)&k1s, g_k1s);
    cudaGetSymbolAddress((void**)&pres, g_pres);
    cudaGetSymbolAddress((void**)&scls, g_scls);
    cudaGetSymbolAddress((void**)&pts, g_pts);

    // 1) splits of inputs
    split_x_kernel<<<dim3(EE / 32, SS / 32, BB), dim3(32, 8)>>>(x);
    split_wv_kernel<<<(unsigned)(WPL / 256), 256>>>(Wqkv);

    // 2) exact q,k values + tile norms (mask decision path, unchanged numerics)
    norm_gemm_kernel<<<dim3(16, 32, 8), 256>>>(x, Wqkv, bqkv);

    // 3) WO row norms + medians
    row_norm_kernel<<<(BB * NROWS) / 8, 256>>>(WO);
    sel_init_kernel<<<32, 256>>>();
    hist_kernel<<<dim3(32, 8), 256>>>(21, 0x00000000u, 2048);
    pick_kernel<<<16, 256>>>(21, 2048);
    hist_kernel<<<dim3(32, 8), 256>>>(10, 0xFFE00000u, 2048);
    pick_kernel<<<16, 256>>>(10, 2048);
    hist_kernel<<<dim3(32, 8), 256>>>(0, 0xFFFFFC00u, 1024);
    pick_kernel<<<16, 256>>>(0, 1024);
    thr_kernel<<<1, 32>>>();
    median_rows_kernel<<<BB, 1024>>>();

    // 4) mask + split pruned operands
    mask_split_qk_kernel<<<(unsigned)(((size_t)BB * SS * 2048) / 256), 256>>>();
    mask_split_wo_kernel<<<(unsigned)(((size_t)BB * SS * EE) / 256), 256>>>(WO);

    // 5) v = x @ Wv^T + bv  -> v splits
    gemm2_kernel<false, true><<<dim3(8, 16, BB), 256, SMEM_BYTES>>>(
        xs, XPL, sXE, wvs, WPL, 0, vs, XPL, sXE, nullptr, 0,
        EE, EE, 1.0f, bqkv + 2 * EE);

    // 6) q_ = x @ qp^T ; k_ = x @ kp^T  -> splits
    gemm2_kernel<false, false><<<dim3(16, 16, BB), 256, SMEM_BYTES>>>(
        xs, XPL, sXE, qs, XPL, sXE, q1s, SQPL, sSQ, nullptr, 0,
        SS, EE, 1.0f, nullptr);
    gemm2_kernel<false, false><<<dim3(16, 16, BB), 256, SMEM_BYTES>>>(
        xs, XPL, sXE, ks, XPL, sXE, k1s, SQPL, sSQ, nullptr, 0,
        SS, EE, 1.0f, nullptr);

    // 7) pre = v @ WOp^T -> splits
    gemm2_kernel<false, false><<<dim3(16, 16, BB), 256, SMEM_BYTES>>>(
        vs, XPL, sXE, wos, XPL, sXE, pres, SQPL, sSQ, nullptr, 0,
        SS, EE, 1.0f, nullptr);

    // 8) scl = (q_ @ k_^T) / 32 -> splits
    gemm2_kernel<false, false><<<dim3(16, 16, BB), 256, SMEM_BYTES>>>(
        q1s, SQPL, sSQ, k1s, SQPL, sSQ, scls, SQPL, sSQ, nullptr, 0,
        SS, SS, 0.03125f, nullptr);

    // 9) proT = xT @ pre^T -> splits   (proT[e][i] = sum_k xT[e][k] * pre[i][k])
    gemm2_kernel<false, false><<<dim3(16, 8, BB), 256, SMEM_BYTES>>>(
        xts, XPL, sES, pres, SQPL, sSQ, pts, XPL, sES, nullptr, 0,
        SS, SS, 1.0f, nullptr);

    // 10) out = scl @ proT^T -> fp32
    gemm2_kernel<true, false><<<dim3(8, 16, BB), 256, SMEM_BYTES>>>(
        scls, SQPL, sSQ, pts, XPL, sES, nullptr, 0, 0, out, sXE,
        EE, SS, 1.0f, nullptr);
}